// round 7
// baseline (speedup 1.0000x reference)
#include <cuda_runtime.h>
#include <cuda_fp16.h>
#include <cstddef>

// Problem constants (B=16, N=M=1024, D=32)
#define CELEM (16 * 1024 * 1024)
#define ROWS  (16 * 1024)
#define NBLK  128                  // persistent blocks (<= SM count, co-resident)

// eps = 1e-3
#define K2F       1442.6951f       // log2(e)/eps
#define EPSLN2F   6.9314718e-4f    // eps*ln2
#define EPSLOGMU  (-6.9314616e-3f) // eps*log(1/1024 + 1e-8)
#define MARGIN    1.2f             // fp16 prefilter margin (E<=0.35 budget + drift)
#define CUM_MAX   0.2f             // max cumulative dual drift before mask rebuild

// Device scratch (allocation-free rule)
__device__ float  g_C  [CELEM];    // fp32 C  (exact pass + final)
__device__ float  g_CT [CELEM];    // fp32 C^T
__device__ __half g_Ch [CELEM];    // fp16 C  (prefilter scan)
__device__ __half g_CTh[CELEM];    // fp16 C^T
__device__ float  g_u[ROWS], g_v[ROWS];
__device__ uint4  g_mask_u[ROWS];  // per-row candidate ballots (u-scan direction)
__device__ uint4  g_mask_v[ROWS];
__device__ float  g_bp[NBLK];      // per-block sum|du|
__device__ float  g_bpmU[NBLK];    // per-block max|du|
__device__ float  g_bpmV[NBLK];    // per-block max|dv|
__device__ int    g_bar_count;
__device__ volatile int g_bar_gen;

// ---------------------------------------------------------------------------
// Software global barrier across NBLK co-resident blocks.
// ---------------------------------------------------------------------------
__device__ __forceinline__ void gbarrier() {
    __syncthreads();
    if (threadIdx.x == 0) {
        __threadfence();
        int gen = g_bar_gen;
        if (atomicAdd(&g_bar_count, 1) == NBLK - 1) {
            g_bar_count = 0;
            __threadfence();
            g_bar_gen = gen + 1;
        } else {
            while (g_bar_gen == gen) __nanosleep(64);
        }
        __threadfence();
    }
    __syncthreads();
}

__device__ __forceinline__ float wred_max(float v) {
#pragma unroll
    for (int o = 16; o; o >>= 1) v = fmaxf(v, __shfl_xor_sync(0xffffffffu, v, o));
    return v;
}
__device__ __forceinline__ float wred_sum(float v) {
#pragma unroll
    for (int o = 16; o; o >>= 1) v += __shfl_xor_sync(0xffffffffu, v, o);
    return v;
}

// fp16 prefilter of group Q (8 elements): DST = max_j (w_j - C_rj)
#define PREF_GRP(Q, DST) do {                                                   \
    uint4 cq = cp[((Q) << 5) + lane];                                           \
    half2 d0 = __hsub2(w2[(Q)*4+0], *reinterpret_cast<const half2*>(&cq.x));    \
    half2 d1 = __hsub2(w2[(Q)*4+1], *reinterpret_cast<const half2*>(&cq.y));    \
    half2 d2 = __hsub2(w2[(Q)*4+2], *reinterpret_cast<const half2*>(&cq.z));    \
    half2 d3 = __hsub2(w2[(Q)*4+3], *reinterpret_cast<const half2*>(&cq.w));    \
    half2 mx = __hmax2(__hmax2(d0, d1), __hmax2(d2, d3));                       \
    DST = fmaxf(__low2float(mx), __high2float(mx));                             \
} while (0)

#define BUILD_W2() do {                                                         \
    _Pragma("unroll")                                                           \
    for (int q = 0; q < 4; q++) {                                               \
        float4 wa = ws4[(q << 6) + (lane << 1)];                                \
        float4 wb = ws4[(q << 6) + (lane << 1) + 1];                            \
        w2[q*4+0] = __floats2half2_rn(wa.x, wa.y);                              \
        w2[q*4+1] = __floats2half2_rn(wa.z, wa.w);                              \
        w2[q*4+2] = __floats2half2_rn(wb.x, wb.y);                              \
        w2[q*4+3] = __floats2half2_rn(wb.z, wb.w);                              \
    }                                                                           \
} while (0)

// ---------------------------------------------------------------------------
// Cost matrix (verified): fp32 + fp16, plus transposes.
// ---------------------------------------------------------------------------
__global__ void __launch_bounds__(256) k_cost(const float* __restrict__ X,
                                              const float* __restrict__ Y) {
    __shared__ float xs[32][33], ys[32][33], cs[32][33];
    int t  = blockIdx.x;
    int b  = t >> 10;
    int it = (t >> 5) & 31;
    int jt = t & 31;
    int tid = threadIdx.x;
    int r = tid >> 5, d = tid & 31;

#pragma unroll
    for (int k = 0; k < 4; k++) {
        int rr = r + (k << 3);
        xs[rr][d] = X[((size_t)b * 1024 + it * 32 + rr) * 32 + d];
        ys[rr][d] = Y[((size_t)b * 1024 + jt * 32 + rr) * 32 + d];
    }
    __syncthreads();

    int tx = tid & 31, ty = tid >> 5;
#pragma unroll
    for (int k = 0; k < 4; k++) {
        int i = ty * 4 + k;
        float acc = 0.f;
#pragma unroll
        for (int dd = 0; dd < 32; dd++) {
            float diff = xs[i][dd] - ys[tx][dd];
            acc = fmaf(diff, diff, acc);
        }
        cs[i][tx] = acc;
    }
    __syncthreads();

    size_t cbase = (size_t)b << 20;
#pragma unroll
    for (int k = 0; k < 4; k++) {
        int i = ty * 4 + k;
        size_t idx  = cbase + (size_t)(it * 32 + i) * 1024 + jt * 32 + tx;
        size_t idxT = cbase + (size_t)(jt * 32 + i) * 1024 + it * 32 + tx;
        float  cv  = cs[i][tx];
        float  cvT = cs[tx][i];
        g_C  [idx]  = cv;
        g_CT [idxT] = cvT;
        g_Ch [idx]  = __float2half_rn(cv);
        g_CTh[idxT] = __float2half_rn(cvT);
    }
}

// ---------------------------------------------------------------------------
// FULL half-step: fp16 prefilter -> rebuild candidate masks -> exact fp32 max
// + exp-sum over flagged groups. Writes z and |dz| (du_s).
// ---------------------------------------------------------------------------
__device__ __forceinline__ void scan_full(
    int bid, int tid, int lane, int wid,
    const __half* __restrict__ Ch, const float* __restrict__ Cf,
    const float* __restrict__ wsrc, float* __restrict__ zdst,
    uint4* __restrict__ Mask,
    float* ws, float* du_s)
{
    int b = bid >> 3;
    ws[tid] = wsrc[(b << 10) + tid];
    __syncthreads();

    const float4* ws4 = (const float4*)ws;
    half2 w2[16];
    BUILD_W2();

#pragma unroll 1
    for (int r = 0; r < 4; r++) {
        int rl  = (wid << 2) + r;
        int row = (bid << 7) + rl;
        const uint4*  cp  = (const uint4*) (Ch + ((size_t)row << 10));
        const float4* cf4 = (const float4*)(Cf + ((size_t)row << 10));

        float gm0, gm1, gm2, gm3;
        PREF_GRP(0, gm0); PREF_GRP(1, gm1); PREF_GRP(2, gm2); PREF_GRP(3, gm3);

        float mrow = wred_max(fmaxf(fmaxf(gm0, gm1), fmaxf(gm2, gm3)));
        float thr  = mrow - MARGIN;
        int msk = (gm0 > thr) | ((gm1 > thr) << 1) | ((gm2 > thr) << 2) | ((gm3 > thr) << 3);

        unsigned b0 = __ballot_sync(0xffffffffu, msk & 1);
        unsigned b1 = __ballot_sync(0xffffffffu, msk & 2);
        unsigned b2b = __ballot_sync(0xffffffffu, msk & 4);
        unsigned b3 = __ballot_sync(0xffffffffu, msk & 8);
        if (lane == 0) Mask[row] = make_uint4(b0, b1, b2b, b3);

        float me = -3.4e38f;
#pragma unroll 1
        for (int q = 0; q < 4; q++) if ((msk >> q) & 1) {
            int ix = (q << 6) + (lane << 1);
            float4 a  = cf4[ix],  bb = cf4[ix + 1];
            float4 wa = ws4[ix],  wb = ws4[ix + 1];
            me = fmaxf(me, fmaxf(fmaxf(wa.x - a.x,  wa.y - a.y),
                                 fmaxf(wa.z - a.z,  wa.w - a.w)));
            me = fmaxf(me, fmaxf(fmaxf(wb.x - bb.x, wb.y - bb.y),
                                 fmaxf(wb.z - bb.z, wb.w - bb.w)));
        }
        me = wred_max(me);

        float s = 0.f;
#pragma unroll 1
        for (int q = 0; q < 4; q++) if ((msk >> q) & 1) {
            int ix = (q << 6) + (lane << 1);
            float4 a  = cf4[ix],  bb = cf4[ix + 1];
            float4 wa = ws4[ix],  wb = ws4[ix + 1];
            s += exp2f((wa.x - a.x  - me) * K2F) + exp2f((wa.y - a.y  - me) * K2F)
               + exp2f((wa.z - a.z  - me) * K2F) + exp2f((wa.w - a.w  - me) * K2F)
               + exp2f((wb.x - bb.x - me) * K2F) + exp2f((wb.y - bb.y - me) * K2F)
               + exp2f((wb.z - bb.z - me) * K2F) + exp2f((wb.w - bb.w - me) * K2F);
        }
        s = wred_sum(s);

        if (lane == 0) {
            float z = EPSLOGMU - me - EPSLN2F * log2f(s);
            du_s[rl] = fabsf(z - zdst[row]);
            zdst[row] = z;
        }
    }
}

// ---------------------------------------------------------------------------
// CHEAP half-step: reuse cached masks; exact fp32 work over flagged groups
// only. 4-row ILP; reductions interleaved to hide shfl latency.
// Sound while cumulative dual drift < CUM_MAX (guarded by caller).
// ---------------------------------------------------------------------------
__device__ __forceinline__ void scan_cheap(
    int bid, int tid, int lane, int wid,
    const float* __restrict__ Cf,
    const uint4* __restrict__ Mask,
    const float* __restrict__ wsrc, float* __restrict__ zdst,
    float* ws, float* du_s)
{
    int b = bid >> 3;
    ws[tid] = wsrc[(b << 10) + tid];
    __syncthreads();
    const float4* ws4 = (const float4*)ws;

    uint4 mk[4];
    const float4* cf4[4];
    float me[4], ss[4];
#pragma unroll
    for (int r = 0; r < 4; r++) {
        int row = (bid << 7) + (wid << 2) + r;
        mk[r]  = Mask[row];                                  // broadcast LDG.128
        cf4[r] = (const float4*)(Cf + ((size_t)row << 10));
        me[r]  = -3.4e38f;
        ss[r]  = 0.f;
    }

    // exact max over flagged (q,lane) cells, 4 rows interleaved
#pragma unroll
    for (int r = 0; r < 4; r++) {
        unsigned wq[4] = { mk[r].x, mk[r].y, mk[r].z, mk[r].w };
#pragma unroll
        for (int q = 0; q < 4; q++) if ((wq[q] >> lane) & 1u) {
            int ix = (q << 6) + (lane << 1);
            float4 a  = cf4[r][ix],  bb = cf4[r][ix + 1];
            float4 wa = ws4[ix],     wb = ws4[ix + 1];
            me[r] = fmaxf(me[r], fmaxf(fmaxf(wa.x - a.x,  wa.y - a.y),
                                       fmaxf(wa.z - a.z,  wa.w - a.w)));
            me[r] = fmaxf(me[r], fmaxf(fmaxf(wb.x - bb.x, wb.y - bb.y),
                                       fmaxf(wb.z - bb.z, wb.w - bb.w)));
        }
    }
#pragma unroll
    for (int o = 16; o; o >>= 1) {
#pragma unroll
        for (int r = 0; r < 4; r++)
            me[r] = fmaxf(me[r], __shfl_xor_sync(0xffffffffu, me[r], o));
    }

    // exp-sum over the same cells (fp32 reload = L1 hit), 4 rows interleaved
#pragma unroll
    for (int r = 0; r < 4; r++) {
        unsigned wq[4] = { mk[r].x, mk[r].y, mk[r].z, mk[r].w };
#pragma unroll
        for (int q = 0; q < 4; q++) if ((wq[q] >> lane) & 1u) {
            int ix = (q << 6) + (lane << 1);
            float4 a  = cf4[r][ix],  bb = cf4[r][ix + 1];
            float4 wa = ws4[ix],     wb = ws4[ix + 1];
            float m = me[r];
            ss[r] += exp2f((wa.x - a.x  - m) * K2F) + exp2f((wa.y - a.y  - m) * K2F)
                   + exp2f((wa.z - a.z  - m) * K2F) + exp2f((wa.w - a.w  - m) * K2F)
                   + exp2f((wb.x - bb.x - m) * K2F) + exp2f((wb.y - bb.y - m) * K2F)
                   + exp2f((wb.z - bb.z - m) * K2F) + exp2f((wb.w - bb.w - m) * K2F);
        }
    }
#pragma unroll
    for (int o = 16; o; o >>= 1) {
#pragma unroll
        for (int r = 0; r < 4; r++)
            ss[r] += __shfl_xor_sync(0xffffffffu, ss[r], o);
    }

    if (lane == 0) {
#pragma unroll
        for (int r = 0; r < 4; r++) {
            int rl  = (wid << 2) + r;
            int row = (bid << 7) + rl;
            float z = EPSLOGMU - me[r] - EPSLN2F * log2f(ss[r]);
            du_s[rl] = fabsf(z - zdst[row]);
            zdst[row] = z;
        }
    }
}

// Block epilogue: reduce du_s -> per-block sum (u only) + max.
__device__ __forceinline__ void blk_epi(int bid, int lane, int wid,
                                        const float* du_s, bool is_u) {
    __syncthreads();
    if (wid == 0) {
        float a = du_s[lane], b = du_s[lane + 32], c = du_s[lane + 64], d = du_s[lane + 96];
        float sum = wred_sum(a + b + c + d);
        float mx  = wred_max(fmaxf(fmaxf(a, b), fmaxf(c, d)));
        if (lane == 0) {
            if (is_u) { g_bp[bid] = sum; g_bpmU[bid] = mx; }
            else      { g_bpmV[bid] = mx; }
        }
    }
}

// ---------------------------------------------------------------------------
// Persistent Sinkhorn kernel.
// ---------------------------------------------------------------------------
__global__ void __launch_bounds__(1024, 1) k_sink(float* __restrict__ out) {
    __shared__ float ws[1024];
    __shared__ float du_s[128];
    __shared__ float s_red[2];
    int tid  = threadIdx.x, bid = blockIdx.x;
    int lane = tid & 31,    wid = tid >> 5;

    if (tid < 128) { int r = (bid << 7) + tid; g_u[r] = 0.f; g_v[r] = 0.f; }
    gbarrier();

    float cum_u = 1e30f, cum_v = 1e30f;   // drift since M_v / M_u were built
    bool  will_done = false;

    for (int it = 0; it < 100; it++) {
        // ---- u-update ----
        bool full_u = (cum_v > CUM_MAX);
        if (full_u) {
            cum_v = 0.f;
            scan_full (bid, tid, lane, wid, g_Ch, g_C, g_v, g_u, g_mask_u, ws, du_s);
        } else {
            scan_cheap(bid, tid, lane, wid, g_C, g_mask_u, g_v, g_u, ws, du_s);
        }
        blk_epi(bid, lane, wid, du_s, true);
        gbarrier();

        // all blocks identically: err + max|du|
        if (tid < 32) {
            float a = g_bp[lane] + g_bp[lane + 32] + g_bp[lane + 64] + g_bp[lane + 96];
            a = wred_sum(a);
            float m = fmaxf(fmaxf(g_bpmU[lane], g_bpmU[lane + 32]),
                            fmaxf(g_bpmU[lane + 64], g_bpmU[lane + 96]));
            m = wred_max(m);
            if (lane == 0) { s_red[0] = a; s_red[1] = m; }
        }
        __syncthreads();
        will_done = (s_red[0] * (1.0f / 16.0f) < 0.1f);
        cum_u += s_red[1];
        __syncthreads();

        // ---- v-update (triggering iteration's v still applied) ----
        bool full_v = (cum_u > CUM_MAX);
        if (full_v) {
            cum_u = 0.f;
            scan_full (bid, tid, lane, wid, g_CTh, g_CT, g_u, g_v, g_mask_v, ws, du_s);
        } else {
            scan_cheap(bid, tid, lane, wid, g_CT, g_mask_v, g_u, g_v, ws, du_s);
        }
        blk_epi(bid, lane, wid, du_s, false);
        gbarrier();

        if (tid < 32) {
            float m = fmaxf(fmaxf(g_bpmV[lane], g_bpmV[lane + 32]),
                            fmaxf(g_bpmV[lane + 64], g_bpmV[lane + 96]));
            m = wred_max(m);
            if (lane == 0) s_red[1] = m;
        }
        __syncthreads();
        cum_v += s_red[1];

        if (will_done) break;   // uniform across blocks (identical reductions)
    }

    // --------- final: sum_ij exp((u_i + v_j - C_ij)/eps) * C_ij ----------
    {
        int b = bid >> 3;
        ws[tid] = g_v[(b << 10) + tid];
        __syncthreads();
        const float4* ws4 = (const float4*)ws;
        half2 w2[16];
        BUILD_W2();

#pragma unroll 1
        for (int r = 0; r < 4; r++) {
            int rl  = (wid << 2) + r;
            int row = (bid << 7) + rl;
            const uint4*  cp  = (const uint4*) (g_Ch + ((size_t)row << 10));
            const float4* cf4 = (const float4*)(g_C  + ((size_t)row << 10));
            float uk = g_u[row];

            float gm0, gm1, gm2, gm3;
            PREF_GRP(0, gm0); PREF_GRP(1, gm1); PREF_GRP(2, gm2); PREF_GRP(3, gm3);

            float cut = -0.65f - uk;
            int msk = (gm0 > cut) | ((gm1 > cut) << 1) | ((gm2 > cut) << 2) | ((gm3 > cut) << 3);

            float s = 0.f;
#pragma unroll 1
            for (int q = 0; q < 4; q++) if ((msk >> q) & 1) {
                int ix = (q << 6) + (lane << 1);
                float4 a  = cf4[ix],  bb = cf4[ix + 1];
                float4 wa = ws4[ix],  wb = ws4[ix + 1];
                s += exp2f((wa.x - a.x  + uk) * K2F) * a.x
                   + exp2f((wa.y - a.y  + uk) * K2F) * a.y
                   + exp2f((wa.z - a.z  + uk) * K2F) * a.z
                   + exp2f((wa.w - a.w  + uk) * K2F) * a.w
                   + exp2f((wb.x - bb.x + uk) * K2F) * bb.x
                   + exp2f((wb.y - bb.y + uk) * K2F) * bb.y
                   + exp2f((wb.z - bb.z + uk) * K2F) * bb.z
                   + exp2f((wb.w - bb.w + uk) * K2F) * bb.w;
            }
            s = wred_sum(s);
            if (lane == 0) du_s[rl] = s;
        }
        __syncthreads();
        if (wid == 0) {
            float e = du_s[lane] + du_s[lane + 32] + du_s[lane + 64] + du_s[lane + 96];
            e = wred_sum(e);
            if (lane == 0) g_bp[bid] = e;
        }
    }
    gbarrier();
    if (bid == 0 && wid == 0) {
        float e = g_bp[lane] + g_bp[lane + 32] + g_bp[lane + 64] + g_bp[lane + 96];
        e = wred_sum(e);
        if (lane == 0) out[0] = e * (1.0f / 16.0f);
    }
}

// ---------------------------------------------------------------------------
extern "C" void kernel_launch(void* const* d_in, const int* in_sizes, int n_in,
                              void* d_out, int out_size) {
    (void)in_sizes; (void)n_in; (void)out_size;
    const float* X = (const float*)d_in[0];   // output [16,1024,32]
    const float* Y = (const float*)d_in[1];   // labels [16,1024,32]

    k_cost<<<16384, 256>>>(X, Y);
    k_sink<<<NBLK, 1024>>>((float*)d_out);
}

// round 8
// speedup vs baseline: 1.1108x; 1.1108x over previous
#include <cuda_runtime.h>
#include <cuda_fp16.h>
#include <cstddef>

// Problem constants (B=16, N=M=1024, D=32)
#define CELEM (16 * 1024 * 1024)
#define ROWS  (16 * 1024)
#define NBLK  128                  // persistent blocks (co-resident)

// eps = 1e-3
#define K2F       1442.6951f       // log2(e)/eps
#define EPSLN2F   6.9314718e-4f    // eps*ln2
#define EPSLOGMU  (-6.9314616e-3f) // eps*log(1/1024 + 1e-8)
#define MARGIN_X  0.6f             // exact-pass prefilter margin (proven R5/R6)
#define MARGIN_S  1.0f             // stored-mask margin (covers 2E + 2*CUM_MAX + 0.03)
#define CUM_MAX   0.1f             // max cumulative dual drift before mask rebuild

// Device scratch (allocation-free rule)
__device__ float  g_C  [CELEM];    // fp32 C
__device__ float  g_CT [CELEM];    // fp32 C^T
__device__ __half g_Ch [CELEM];    // fp16 C  (prefilter)
__device__ __half g_CTh[CELEM];    // fp16 C^T
__device__ float  g_u[ROWS], g_v[ROWS];
__device__ uint4  g_mask_u[ROWS];  // cached candidate ballots (u-scan)
__device__ uint4  g_mask_v[ROWS];
__device__ float  g_bp[NBLK];      // per-block sum|du|
__device__ float  g_bpmU[NBLK];    // per-block max|du|
__device__ float  g_bpmV[NBLK];    // per-block max|dv|
__device__ int    g_bar_count;
__device__ volatile int g_bar_gen;

// ---------------------------------------------------------------------------
__device__ __forceinline__ void gbarrier() {
    __syncthreads();
    if (threadIdx.x == 0) {
        __threadfence();
        int gen = g_bar_gen;
        if (atomicAdd(&g_bar_count, 1) == NBLK - 1) {
            g_bar_count = 0;
            __threadfence();
            g_bar_gen = gen + 1;
        } else {
            while (g_bar_gen == gen) __nanosleep(64);
        }
        __threadfence();
    }
    __syncthreads();
}

__device__ __forceinline__ float wred_max(float v) {
#pragma unroll
    for (int o = 16; o; o >>= 1) v = fmaxf(v, __shfl_xor_sync(0xffffffffu, v, o));
    return v;
}
__device__ __forceinline__ float wred_sum(float v) {
#pragma unroll
    for (int o = 16; o; o >>= 1) v += __shfl_xor_sync(0xffffffffu, v, o);
    return v;
}

#define PREF_GRP(Q, DST) do {                                                   \
    uint4 cq = cp[((Q) << 5) + lane];                                           \
    half2 d0 = __hsub2(w2[(Q)*4+0], *reinterpret_cast<const half2*>(&cq.x));    \
    half2 d1 = __hsub2(w2[(Q)*4+1], *reinterpret_cast<const half2*>(&cq.y));    \
    half2 d2 = __hsub2(w2[(Q)*4+2], *reinterpret_cast<const half2*>(&cq.z));    \
    half2 d3 = __hsub2(w2[(Q)*4+3], *reinterpret_cast<const half2*>(&cq.w));    \
    half2 mx = __hmax2(__hmax2(d0, d1), __hmax2(d2, d3));                       \
    DST = fmaxf(__low2float(mx), __high2float(mx));                             \
} while (0)

#define BUILD_W2() do {                                                         \
    _Pragma("unroll")                                                           \
    for (int q = 0; q < 4; q++) {                                               \
        float4 wa = ws4[(q << 6) + (lane << 1)];                                \
        float4 wb = ws4[(q << 6) + (lane << 1) + 1];                            \
        w2[q*4+0] = __floats2half2_rn(wa.x, wa.y);                              \
        w2[q*4+1] = __floats2half2_rn(wa.z, wa.w);                              \
        w2[q*4+2] = __floats2half2_rn(wb.x, wb.y);                              \
        w2[q*4+3] = __floats2half2_rn(wb.z, wb.w);                              \
    }                                                                           \
} while (0)

// ---------------------------------------------------------------------------
// Cost matrix (verified): fp32 + fp16, plus transposes.
// ---------------------------------------------------------------------------
__global__ void __launch_bounds__(256) k_cost(const float* __restrict__ X,
                                              const float* __restrict__ Y) {
    __shared__ float xs[32][33], ys[32][33], cs[32][33];
    int t  = blockIdx.x;
    int b  = t >> 10;
    int it = (t >> 5) & 31;
    int jt = t & 31;
    int tid = threadIdx.x;
    int r = tid >> 5, d = tid & 31;

#pragma unroll
    for (int k = 0; k < 4; k++) {
        int rr = r + (k << 3);
        xs[rr][d] = X[((size_t)b * 1024 + it * 32 + rr) * 32 + d];
        ys[rr][d] = Y[((size_t)b * 1024 + jt * 32 + rr) * 32 + d];
    }
    __syncthreads();

    int tx = tid & 31, ty = tid >> 5;
#pragma unroll
    for (int k = 0; k < 4; k++) {
        int i = ty * 4 + k;
        float acc = 0.f;
#pragma unroll
        for (int dd = 0; dd < 32; dd++) {
            float diff = xs[i][dd] - ys[tx][dd];
            acc = fmaf(diff, diff, acc);
        }
        cs[i][tx] = acc;
    }
    __syncthreads();

    size_t cbase = (size_t)b << 20;
#pragma unroll
    for (int k = 0; k < 4; k++) {
        int i = ty * 4 + k;
        size_t idx  = cbase + (size_t)(it * 32 + i) * 1024 + jt * 32 + tx;
        size_t idxT = cbase + (size_t)(jt * 32 + i) * 1024 + it * 32 + tx;
        float  cv  = cs[i][tx];
        float  cvT = cs[tx][i];
        g_C  [idx]  = cv;
        g_CT [idxT] = cvT;
        g_Ch [idx]  = __float2half_rn(cv);
        g_CTh[idxT] = __float2half_rn(cvT);
    }
}

// ---------------------------------------------------------------------------
// FULL half-step: fp16 prefilter; exact pass over NARROW (0.6) mask;
// store WIDE (1.0) mask for cheap reuse.
// ---------------------------------------------------------------------------
__device__ __forceinline__ void scan_full(
    int bid, int tid, int lane, int wid,
    const __half* __restrict__ Ch, const float* __restrict__ Cf,
    const float* __restrict__ wsrc, float* __restrict__ zdst,
    uint4* __restrict__ Mask,
    float* ws, float* du_s)
{
    int b = bid >> 3;
    ws[tid] = wsrc[(b << 10) + tid];
    __syncthreads();

    const float4* ws4 = (const float4*)ws;
    half2 w2[16];
    BUILD_W2();

#pragma unroll 1
    for (int r = 0; r < 4; r++) {
        int rl  = (wid << 2) + r;
        int row = (bid << 7) + rl;
        const uint4*  cp  = (const uint4*) (Ch + ((size_t)row << 10));
        const float4* cf4 = (const float4*)(Cf + ((size_t)row << 10));

        float gm0, gm1, gm2, gm3;
        PREF_GRP(0, gm0); PREF_GRP(1, gm1); PREF_GRP(2, gm2); PREF_GRP(3, gm3);

        float mrow = wred_max(fmaxf(fmaxf(gm0, gm1), fmaxf(gm2, gm3)));

        // narrow mask: exact compute this iteration
        float tx  = mrow - MARGIN_X;
        int msk = (gm0 > tx) | ((gm1 > tx) << 1) | ((gm2 > tx) << 2) | ((gm3 > tx) << 3);
        // wide mask: stored for cheap-iteration reuse
        float tsv = mrow - MARGIN_S;
        int msks = (gm0 > tsv) | ((gm1 > tsv) << 1) | ((gm2 > tsv) << 2) | ((gm3 > tsv) << 3);

        unsigned b0 = __ballot_sync(0xffffffffu, msks & 1);
        unsigned b1 = __ballot_sync(0xffffffffu, msks & 2);
        unsigned b2 = __ballot_sync(0xffffffffu, msks & 4);
        unsigned b3 = __ballot_sync(0xffffffffu, msks & 8);
        if (lane == 0) Mask[row] = make_uint4(b0, b1, b2, b3);

        float me = -3.4e38f;
#pragma unroll 1
        for (int q = 0; q < 4; q++) if ((msk >> q) & 1) {
            int ix = (q << 6) + (lane << 1);
            float4 a  = cf4[ix],  bb = cf4[ix + 1];
            float4 wa = ws4[ix],  wb = ws4[ix + 1];
            me = fmaxf(me, fmaxf(fmaxf(wa.x - a.x,  wa.y - a.y),
                                 fmaxf(wa.z - a.z,  wa.w - a.w)));
            me = fmaxf(me, fmaxf(fmaxf(wb.x - bb.x, wb.y - bb.y),
                                 fmaxf(wb.z - bb.z, wb.w - bb.w)));
        }
        me = wred_max(me);

        float s = 0.f;
#pragma unroll 1
        for (int q = 0; q < 4; q++) if ((msk >> q) & 1) {
            int ix = (q << 6) + (lane << 1);
            float4 a  = cf4[ix],  bb = cf4[ix + 1];
            float4 wa = ws4[ix],  wb = ws4[ix + 1];
            s += exp2f((wa.x - a.x  - me) * K2F) + exp2f((wa.y - a.y  - me) * K2F)
               + exp2f((wa.z - a.z  - me) * K2F) + exp2f((wa.w - a.w  - me) * K2F)
               + exp2f((wb.x - bb.x - me) * K2F) + exp2f((wb.y - bb.y - me) * K2F)
               + exp2f((wb.z - bb.z - me) * K2F) + exp2f((wb.w - bb.w - me) * K2F);
        }
        s = wred_sum(s);

        if (lane == 0) {
            float z = EPSLOGMU - me - EPSLN2F * log2f(s);
            du_s[rl] = fabsf(z - zdst[row]);
            zdst[row] = z;
        }
    }
}

// ---------------------------------------------------------------------------
// CHEAP half-step: exact fp32 over cached wide mask only.
// Sound while cumulative drift since build <= CUM_MAX (caller-guarded).
// ---------------------------------------------------------------------------
__device__ __forceinline__ void scan_cheap(
    int bid, int tid, int lane, int wid,
    const float* __restrict__ Cf,
    const uint4* __restrict__ Mask,
    const float* __restrict__ wsrc, float* __restrict__ zdst,
    float* ws, float* du_s)
{
    int b = bid >> 3;
    ws[tid] = wsrc[(b << 10) + tid];
    __syncthreads();
    const float4* ws4 = (const float4*)ws;

#pragma unroll 1
    for (int r = 0; r < 4; r++) {
        int rl  = (wid << 2) + r;
        int row = (bid << 7) + rl;
        uint4 mk = Mask[row];
        const float4* cf4 = (const float4*)(Cf + ((size_t)row << 10));
        unsigned wq[4] = { mk.x, mk.y, mk.z, mk.w };

        float me = -3.4e38f;
#pragma unroll 1
        for (int q = 0; q < 4; q++) if ((wq[q] >> lane) & 1u) {
            int ix = (q << 6) + (lane << 1);
            float4 a  = cf4[ix],  bb = cf4[ix + 1];
            float4 wa = ws4[ix],  wb = ws4[ix + 1];
            me = fmaxf(me, fmaxf(fmaxf(wa.x - a.x,  wa.y - a.y),
                                 fmaxf(wa.z - a.z,  wa.w - a.w)));
            me = fmaxf(me, fmaxf(fmaxf(wb.x - bb.x, wb.y - bb.y),
                                 fmaxf(wb.z - bb.z, wb.w - bb.w)));
        }
        me = wred_max(me);

        float s = 0.f;
#pragma unroll 1
        for (int q = 0; q < 4; q++) if ((wq[q] >> lane) & 1u) {
            int ix = (q << 6) + (lane << 1);
            float4 a  = cf4[ix],  bb = cf4[ix + 1];   // L1 hit
            float4 wa = ws4[ix],  wb = ws4[ix + 1];
            s += exp2f((wa.x - a.x  - me) * K2F) + exp2f((wa.y - a.y  - me) * K2F)
               + exp2f((wa.z - a.z  - me) * K2F) + exp2f((wa.w - a.w  - me) * K2F)
               + exp2f((wb.x - bb.x - me) * K2F) + exp2f((wb.y - bb.y - me) * K2F)
               + exp2f((wb.z - bb.z - me) * K2F) + exp2f((wb.w - bb.w - me) * K2F);
        }
        s = wred_sum(s);

        if (lane == 0) {
            float z = EPSLOGMU - me - EPSLN2F * log2f(s);
            du_s[rl] = fabsf(z - zdst[row]);
            zdst[row] = z;
        }
    }
}

// Block epilogue: reduce du_s -> per-block sum (u only) + max.
__device__ __forceinline__ void blk_epi(int bid, int lane, int wid,
                                        const float* du_s, bool is_u) {
    __syncthreads();
    if (wid == 0) {
        float a = du_s[lane], b = du_s[lane + 32], c = du_s[lane + 64], d = du_s[lane + 96];
        float sum = wred_sum(a + b + c + d);
        float mx  = wred_max(fmaxf(fmaxf(a, b), fmaxf(c, d)));
        if (lane == 0) {
            if (is_u) { g_bp[bid] = sum; g_bpmU[bid] = mx; }
            else      { g_bpmV[bid] = mx; }
        }
    }
}

// ---------------------------------------------------------------------------
// Persistent Sinkhorn kernel.
// ---------------------------------------------------------------------------
__global__ void __launch_bounds__(1024, 1) k_sink(float* __restrict__ out) {
    __shared__ float ws[1024];
    __shared__ float du_s[128];
    __shared__ float s_red[2];
    int tid  = threadIdx.x, bid = blockIdx.x;
    int lane = tid & 31,    wid = tid >> 5;

    if (tid < 128) { int r = (bid << 7) + tid; g_u[r] = 0.f; g_v[r] = 0.f; }
    gbarrier();

    float cum_u = 1e30f, cum_v = 1e30f;   // drift since masks were built
    bool  will_done = false;

    for (int it = 0; it < 100; it++) {
        // ---- u-update (reads v; mask validity tied to v drift) ----
        if (cum_v > CUM_MAX) {
            cum_v = 0.f;
            scan_full (bid, tid, lane, wid, g_Ch, g_C, g_v, g_u, g_mask_u, ws, du_s);
        } else {
            scan_cheap(bid, tid, lane, wid, g_C, g_mask_u, g_v, g_u, ws, du_s);
        }
        blk_epi(bid, lane, wid, du_s, true);
        gbarrier();

        if (tid < 32) {
            float a = g_bp[lane] + g_bp[lane + 32] + g_bp[lane + 64] + g_bp[lane + 96];
            a = wred_sum(a);
            float m = fmaxf(fmaxf(g_bpmU[lane], g_bpmU[lane + 32]),
                            fmaxf(g_bpmU[lane + 64], g_bpmU[lane + 96]));
            m = wred_max(m);
            if (lane == 0) { s_red[0] = a; s_red[1] = m; }
        }
        __syncthreads();
        will_done = (s_red[0] * (1.0f / 16.0f) < 0.1f);
        cum_u += s_red[1];
        __syncthreads();

        // ---- v-update (triggering iteration's v still applied) ----
        if (cum_u > CUM_MAX) {
            cum_u = 0.f;
            scan_full (bid, tid, lane, wid, g_CTh, g_CT, g_u, g_v, g_mask_v, ws, du_s);
        } else {
            scan_cheap(bid, tid, lane, wid, g_CT, g_mask_v, g_u, g_v, ws, du_s);
        }
        blk_epi(bid, lane, wid, du_s, false);
        gbarrier();

        if (tid < 32) {
            float m = fmaxf(fmaxf(g_bpmV[lane], g_bpmV[lane + 32]),
                            fmaxf(g_bpmV[lane + 64], g_bpmV[lane + 96]));
            m = wred_max(m);
            if (lane == 0) s_red[1] = m;
        }
        __syncthreads();
        cum_v += s_red[1];

        if (will_done) break;   // uniform across blocks
    }

    // --------- final: sum_ij exp((u_i + v_j - C_ij)/eps) * C_ij ----------
    {
        int b = bid >> 3;
        ws[tid] = g_v[(b << 10) + tid];
        __syncthreads();
        const float4* ws4 = (const float4*)ws;
        half2 w2[16];
        BUILD_W2();

#pragma unroll 1
        for (int r = 0; r < 4; r++) {
            int rl  = (wid << 2) + r;
            int row = (bid << 7) + rl;
            const uint4*  cp  = (const uint4*) (g_Ch + ((size_t)row << 10));
            const float4* cf4 = (const float4*)(g_C  + ((size_t)row << 10));
            float uk = g_u[row];

            float gm0, gm1, gm2, gm3;
            PREF_GRP(0, gm0); PREF_GRP(1, gm1); PREF_GRP(2, gm2); PREF_GRP(3, gm3);

            float cut = -0.65f - uk;
            int msk = (gm0 > cut) | ((gm1 > cut) << 1) | ((gm2 > cut) << 2) | ((gm3 > cut) << 3);

            float s = 0.f;
#pragma unroll 1
            for (int q = 0; q < 4; q++) if ((msk >> q) & 1) {
                int ix = (q << 6) + (lane << 1);
                float4 a  = cf4[ix],  bb = cf4[ix + 1];
                float4 wa = ws4[ix],  wb = ws4[ix + 1];
                s += exp2f((wa.x - a.x  + uk) * K2F) * a.x
                   + exp2f((wa.y - a.y  + uk) * K2F) * a.y
                   + exp2f((wa.z - a.z  + uk) * K2F) * a.z
                   + exp2f((wa.w - a.w  + uk) * K2F) * a.w
                   + exp2f((wb.x - bb.x + uk) * K2F) * bb.x
                   + exp2f((wb.y - bb.y + uk) * K2F) * bb.y
                   + exp2f((wb.z - bb.z + uk) * K2F) * bb.z
                   + exp2f((wb.w - bb.w + uk) * K2F) * bb.w;
            }
            s = wred_sum(s);
            if (lane == 0) du_s[rl] = s;
        }
        __syncthreads();
        if (wid == 0) {
            float e = du_s[lane] + du_s[lane + 32] + du_s[lane + 64] + du_s[lane + 96];
            e = wred_sum(e);
            if (lane == 0) g_bp[bid] = e;
        }
    }
    gbarrier();
    if (bid == 0 && wid == 0) {
        float e = g_bp[lane] + g_bp[lane + 32] + g_bp[lane + 64] + g_bp[lane + 96];
        e = wred_sum(e);
        if (lane == 0) out[0] = e * (1.0f / 16.0f);
    }
}

// ---------------------------------------------------------------------------
extern "C" void kernel_launch(void* const* d_in, const int* in_sizes, int n_in,
                              void* d_out, int out_size) {
    (void)in_sizes; (void)n_in; (void)out_size;
    const float* X = (const float*)d_in[0];   // output [16,1024,32]
    const float* Y = (const float*)d_in[1];   // labels [16,1024,32]

    k_cost<<<16384, 256>>>(X, Y);
    k_sink<<<NBLK, 1024>>>((float*)d_out);
}